// round 14
// baseline (speedup 1.0000x reference)
#include <cuda_runtime.h>

#define TMAXB 100000
#define TILE  256
#define NT    ((TMAXB + TILE - 1) / TILE)   // 391
#define NB_ACC 1024                          // measured optimum: stride 2^18

// AoS per-bucket accumulators: {x=hz sum, y=ties sum, z=lognom sum, w=event count}
// Zero at module load; pipeline is self-cleaning across graph replays.
__device__ float4 g_b[TMAXB];          // 1.6 MB, L2-resident
__device__ float  g_part[NT];          // per-tile totals of hz
__device__ double g_sum_terms;
__device__ double g_sum_lognom;
__device__ int    g_include;
__device__ unsigned int g_done;        // finalize ticket

// ---------------------------------------------------------------------------
__device__ __forceinline__ void red_v4(float4* p, float a, float b, float c, float d) {
    asm volatile("red.global.add.v4.f32 [%0], {%1,%2,%3,%4};"
                 :: "l"(p), "f"(a), "f"(b), "f"(c), "f"(d) : "memory");
}
__device__ __forceinline__ void red_f32(float* p, float a) {
    asm volatile("red.global.add.f32 [%0], %1;"
                 :: "l"(p), "f"(a) : "memory");
}

__device__ __forceinline__ void accum_one(float x, int t, int e) {
    float h = __expf(x);
    if (e)
        red_v4(&g_b[t], h, h, x, 1.0f);
    else
        red_f32(&g_b[t].x, h);
}

// Exact-divisor grid (1024x256, stride 2^18 divides n4=2^21 -> 8 iters),
// no bounds check; unroll 2 (measured optimum).
__global__ void __launch_bounds__(256) k_accum(
        const float4* __restrict__ lh4,
        const int4*   __restrict__ tt4,
        const int4*   __restrict__ ev4, int n4) {
    const int stride = NB_ACC * 256;
    int i = blockIdx.x * 256 + threadIdx.x;
    int iters = n4 / stride;   // exact: 8
    #pragma unroll 2
    for (int k = 0; k < iters; ++k, i += stride) {
        float4 x = __ldcs(&lh4[i]);
        int4   t = __ldcs(&tt4[i]);
        int4   e = __ldcs(&ev4[i]);
        accum_one(x.x, t.x, e.x);
        accum_one(x.y, t.y, e.y);
        accum_one(x.z, t.z, e.z);
        accum_one(x.w, t.w, e.w);
    }
}

// generic fallback for any leftover range [lo, n)
__global__ void k_accum_tail(const float* __restrict__ lh,
                             const int*   __restrict__ tt,
                             const int*   __restrict__ ev, int lo, int n) {
    int i = lo + blockIdx.x * blockDim.x + threadIdx.x;
    int stride = gridDim.x * blockDim.x;
    for (; i < n; i += stride) accum_one(lh[i], tt[i], ev[i]);
}

// ---------------------------------------------------------------------------
__device__ __forceinline__ float block_reduce_f(float v) {
    __shared__ float sh[8];
    int lane = threadIdx.x & 31, wid = threadIdx.x >> 5;
    #pragma unroll
    for (int o = 16; o > 0; o >>= 1)
        v += __shfl_down_sync(0xffffffffu, v, o);
    if (lane == 0) sh[wid] = v;
    __syncthreads();
    v = (threadIdx.x < 8) ? sh[threadIdx.x] : 0.f;
    if (wid == 0) {
        #pragma unroll
        for (int o = 4; o > 0; o >>= 1)
            v += __shfl_down_sync(0xffffffffu, v, o);
    }
    return v;   // valid in thread 0
}

struct Triple { double a, b, c; };
__device__ __forceinline__ Triple block_reduce_3d(double a, double b, double c) {
    __shared__ double sha[8], shb[8], shc[8];
    int lane = threadIdx.x & 31, wid = threadIdx.x >> 5;
    #pragma unroll
    for (int o = 16; o > 0; o >>= 1) {
        a += __shfl_down_sync(0xffffffffu, a, o);
        b += __shfl_down_sync(0xffffffffu, b, o);
        c += __shfl_down_sync(0xffffffffu, c, o);
    }
    if (lane == 0) { sha[wid] = a; shb[wid] = b; shc[wid] = c; }
    __syncthreads();
    if (threadIdx.x < 8) { a = sha[threadIdx.x]; b = shb[threadIdx.x]; c = shc[threadIdx.x]; }
    else                 { a = 0.0; b = 0.0; c = 0.0; }
    if (wid == 0) {
        #pragma unroll
        for (int o = 4; o > 0; o >>= 1) {
            a += __shfl_down_sync(0xffffffffu, a, o);
            b += __shfl_down_sync(0xffffffffu, b, o);
            c += __shfl_down_sync(0xffffffffu, c, o);
        }
    }
    return {a, b, c};
}

// ---------------------------------------------------------------------------
// Per-tile totals of hz (coalesced reads of g_b[].x)
__global__ void k_part() {
    int b = blockIdx.x;
    int i = b * TILE + threadIdx.x;
    float s = (i < TMAXB) ? g_b[i].x : 0.f;
    s = block_reduce_f(s);
    if (threadIdx.x == 0) g_part[b] = s;
}

// ---------------------------------------------------------------------------
// Fused epilogue (kernel boundary after k_part is the global sync):
//   1) exclusive suffix of tile totals  2) in-tile suffix scan -> D
//   3) Efron terms  4) self-clean + global sums + last-block finalize
__global__ void k_fused(float* __restrict__ out) {
    __shared__ float sa[TILE];
    __shared__ float sb[TILE];
    __shared__ float s_sfx;
    int b = blockIdx.x, tid = threadIdx.x;
    int i = b * TILE + tid;

    // (1) sum of g_part[j] for j > b
    float acc = 0.f;
    for (int j = tid; j < NT; j += TILE)
        if (j > b) acc += g_part[j];
    acc = block_reduce_f(acc);
    if (tid == 0) s_sfx = acc;

    // (2) inclusive suffix scan of tile hz
    float4 bv = (i < TMAXB) ? g_b[i] : make_float4(0.f, 0.f, 0.f, 0.f);
    if (i < TMAXB) g_b[i] = make_float4(0.f, 0.f, 0.f, 0.f);   // self-clean
    sa[tid] = bv.x;
    __syncthreads();
    float* src = sa; float* dst = sb;
    #pragma unroll
    for (int off = 1; off < TILE; off <<= 1) {
        float v = src[tid];
        if (tid + off < TILE) v += src[tid + off];
        dst[tid] = v;
        __syncthreads();
        float* tmp = src; src = dst; dst = tmp;
    }
    float D = src[tid] + s_sfx;   // risk-set sum for bucket i

    // (3) Efron terms
    double local_terms = 0.0, local_lognom = 0.0;
    int cnt = 0;
    int m = (int)(bv.w + 0.5f);
    if (i < TMAXB && m > 0) {
        cnt = 1;
        local_lognom = (double)bv.z;
        float step = bv.y / (float)m;
        float lsum = 0.f;
        int l = 0;
        while (l < m) {
            int lim = (m - l) < 4 ? (m - l) : 4;
            float prod = 1.f;
            #pragma unroll 4
            for (int j = 0; j < lim; ++j)
                prod *= fmaf(-(float)(l + j), step, D);
            lsum += __logf(prod);
            l += lim;
        }
        local_terms = (double)lsum;
    }

    // (4) global sums + last-block finalize
    Triple t = block_reduce_3d(local_terms, local_lognom, (double)cnt);
    if (tid == 0) {
        if (t.a != 0.0) atomicAdd(&g_sum_terms, t.a);
        if (t.b != 0.0) atomicAdd(&g_sum_lognom, t.b);
        int ic = (int)(t.c + 0.5);
        if (ic) atomicAdd(&g_include, ic);
        __threadfence();
        unsigned int ticket = atomicAdd(&g_done, 1u);
        if (ticket == (unsigned)NT - 1u) {
            __threadfence();
            double pll = g_sum_lognom - g_sum_terms;
            out[0] = (float)(-(pll / (double)g_include));
            g_sum_terms = 0.0;
            g_sum_lognom = 0.0;
            g_include = 0;
            g_done = 0u;
        }
    }
}

// ---------------------------------------------------------------------------
extern "C" void kernel_launch(void* const* d_in, const int* in_sizes, int n_in,
                              void* d_out, int out_size) {
    const float* lh = (const float*)d_in[0];
    const int*   tt = (const int*)d_in[1];
    const int*   ev = (const int*)d_in[2];
    float* out = (float*)d_out;
    int n = in_sizes[0];
    int n4 = n / 4;
    const int stride = NB_ACC * 256;
    int main4 = (n4 / stride) * stride;   // exactly covered by k_accum
    int lo = main4 * 4;

    if (main4 > 0)
        k_accum<<<NB_ACC, 256>>>((const float4*)lh, (const int4*)tt,
                                 (const int4*)ev, main4);
    if (lo < n)
        k_accum_tail<<<128, 256>>>(lh, tt, ev, lo, n);

    k_part<<<NT, TILE>>>();
    k_fused<<<NT, TILE>>>(out);
}

// round 15
// speedup vs baseline: 1.4776x; 1.4776x over previous
#include <cuda_runtime.h>

#define TMAXB 100000
#define TILE  256
#define NT    ((TMAXB + TILE - 1) / TILE)   // 391
#define NB_ACC 1024                          // measured optimum: stride 2^18

// AoS per-bucket accumulators: {x=hz sum, y=ties sum, z=lognom sum, w=event count}
// Zero at module load; pipeline is self-cleaning across graph replays.
__device__ float4 g_b[TMAXB];          // 1.6 MB, L2-resident
__device__ float  g_part[NT];          // per-tile totals of hz
__device__ double g_sum_terms;
__device__ double g_sum_lognom;
__device__ int    g_include;
__device__ unsigned int g_done;        // finalize ticket

// ---------------------------------------------------------------------------
__device__ __forceinline__ void red_v4(float4* p, float a, float b, float c, float d) {
    asm volatile("red.global.add.v4.f32 [%0], {%1,%2,%3,%4};"
                 :: "l"(p), "f"(a), "f"(b), "f"(c), "f"(d) : "memory");
}
__device__ __forceinline__ void red_f32(float* p, float a) {
    asm volatile("red.global.add.f32 [%0], %1;"
                 :: "l"(p), "f"(a) : "memory");
}

__device__ __forceinline__ void accum_one(float x, int t, int e) {
    float h = __expf(x);
    if (e)
        red_v4(&g_b[t], h, h, x, 1.0f);
    else
        red_f32(&g_b[t].x, h);
}

// Exact-divisor grid (1024x256, stride 2^18 divides n4=2^21 -> 8 iters),
// no bounds check; unroll 2 (measured optimum).
__global__ void __launch_bounds__(256) k_accum(
        const float4* __restrict__ lh4,
        const int4*   __restrict__ tt4,
        const int4*   __restrict__ ev4, int n4) {
    const int stride = NB_ACC * 256;
    int i = blockIdx.x * 256 + threadIdx.x;
    int iters = n4 / stride;   // exact: 8
    #pragma unroll 2
    for (int k = 0; k < iters; ++k, i += stride) {
        float4 x = __ldcs(&lh4[i]);
        int4   t = __ldcs(&tt4[i]);
        int4   e = __ldcs(&ev4[i]);
        accum_one(x.x, t.x, e.x);
        accum_one(x.y, t.y, e.y);
        accum_one(x.z, t.z, e.z);
        accum_one(x.w, t.w, e.w);
    }
}

// generic fallback for any leftover range [lo, n)
__global__ void k_accum_tail(const float* __restrict__ lh,
                             const int*   __restrict__ tt,
                             const int*   __restrict__ ev, int lo, int n) {
    int i = lo + blockIdx.x * blockDim.x + threadIdx.x;
    int stride = gridDim.x * blockDim.x;
    for (; i < n; i += stride) accum_one(lh[i], tt[i], ev[i]);
}

// ---------------------------------------------------------------------------
__device__ __forceinline__ float block_reduce_f(float v) {
    __shared__ float sh[8];
    int lane = threadIdx.x & 31, wid = threadIdx.x >> 5;
    #pragma unroll
    for (int o = 16; o > 0; o >>= 1)
        v += __shfl_down_sync(0xffffffffu, v, o);
    if (lane == 0) sh[wid] = v;
    __syncthreads();
    v = (threadIdx.x < 8) ? sh[threadIdx.x] : 0.f;
    if (wid == 0) {
        #pragma unroll
        for (int o = 4; o > 0; o >>= 1)
            v += __shfl_down_sync(0xffffffffu, v, o);
    }
    return v;   // valid in thread 0
}

struct Triple { double a, b, c; };
__device__ __forceinline__ Triple block_reduce_3d(double a, double b, double c) {
    __shared__ double sha[8], shb[8], shc[8];
    int lane = threadIdx.x & 31, wid = threadIdx.x >> 5;
    #pragma unroll
    for (int o = 16; o > 0; o >>= 1) {
        a += __shfl_down_sync(0xffffffffu, a, o);
        b += __shfl_down_sync(0xffffffffu, b, o);
        c += __shfl_down_sync(0xffffffffu, c, o);
    }
    if (lane == 0) { sha[wid] = a; shb[wid] = b; shc[wid] = c; }
    __syncthreads();
    if (threadIdx.x < 8) { a = sha[threadIdx.x]; b = shb[threadIdx.x]; c = shc[threadIdx.x]; }
    else                 { a = 0.0; b = 0.0; c = 0.0; }
    if (wid == 0) {
        #pragma unroll
        for (int o = 4; o > 0; o >>= 1) {
            a += __shfl_down_sync(0xffffffffu, a, o);
            b += __shfl_down_sync(0xffffffffu, b, o);
            c += __shfl_down_sync(0xffffffffu, c, o);
        }
    }
    return {a, b, c};
}

// ---------------------------------------------------------------------------
// Per-tile totals of hz (coalesced reads of g_b[].x)
__global__ void k_part() {
    int b = blockIdx.x;
    int i = b * TILE + threadIdx.x;
    float s = (i < TMAXB) ? g_b[i].x : 0.f;
    s = block_reduce_f(s);
    if (threadIdx.x == 0) g_part[b] = s;
}

// ---------------------------------------------------------------------------
// Fused epilogue (kernel boundary after k_part is the global sync):
//   1) exclusive suffix of tile totals  2) in-tile suffix scan -> D
//   3) Efron terms  4) self-clean + global sums + last-block finalize
__global__ void k_fused(float* __restrict__ out) {
    __shared__ float sa[TILE];
    __shared__ float sb[TILE];
    __shared__ float s_sfx;
    int b = blockIdx.x, tid = threadIdx.x;
    int i = b * TILE + tid;

    // (1) sum of g_part[j] for j > b
    float acc = 0.f;
    for (int j = tid; j < NT; j += TILE)
        if (j > b) acc += g_part[j];
    acc = block_reduce_f(acc);
    if (tid == 0) s_sfx = acc;

    // (2) inclusive suffix scan of tile hz
    float4 bv = (i < TMAXB) ? g_b[i] : make_float4(0.f, 0.f, 0.f, 0.f);
    if (i < TMAXB) g_b[i] = make_float4(0.f, 0.f, 0.f, 0.f);   // self-clean
    sa[tid] = bv.x;
    __syncthreads();
    float* src = sa; float* dst = sb;
    #pragma unroll
    for (int off = 1; off < TILE; off <<= 1) {
        float v = src[tid];
        if (tid + off < TILE) v += src[tid + off];
        dst[tid] = v;
        __syncthreads();
        float* tmp = src; src = dst; dst = tmp;
    }
    float D = src[tid] + s_sfx;   // risk-set sum for bucket i

    // (3) Efron terms
    double local_terms = 0.0, local_lognom = 0.0;
    int cnt = 0;
    int m = (int)(bv.w + 0.5f);
    if (i < TMAXB && m > 0) {
        cnt = 1;
        local_lognom = (double)bv.z;
        float step = bv.y / (float)m;
        float lsum = 0.f;
        int l = 0;
        while (l < m) {
            int lim = (m - l) < 4 ? (m - l) : 4;
            float prod = 1.f;
            #pragma unroll 4
            for (int j = 0; j < lim; ++j)
                prod *= fmaf(-(float)(l + j), step, D);
            lsum += __logf(prod);
            l += lim;
        }
        local_terms = (double)lsum;
    }

    // (4) global sums + last-block finalize
    Triple t = block_reduce_3d(local_terms, local_lognom, (double)cnt);
    if (tid == 0) {
        if (t.a != 0.0) atomicAdd(&g_sum_terms, t.a);
        if (t.b != 0.0) atomicAdd(&g_sum_lognom, t.b);
        int ic = (int)(t.c + 0.5);
        if (ic) atomicAdd(&g_include, ic);
        __threadfence();
        unsigned int ticket = atomicAdd(&g_done, 1u);
        if (ticket == (unsigned)NT - 1u) {
            __threadfence();
            double pll = g_sum_lognom - g_sum_terms;
            out[0] = (float)(-(pll / (double)g_include));
            g_sum_terms = 0.0;
            g_sum_lognom = 0.0;
            g_include = 0;
            g_done = 0u;
        }
    }
}

// ---------------------------------------------------------------------------
extern "C" void kernel_launch(void* const* d_in, const int* in_sizes, int n_in,
                              void* d_out, int out_size) {
    const float* lh = (const float*)d_in[0];
    const int*   tt = (const int*)d_in[1];
    const int*   ev = (const int*)d_in[2];
    float* out = (float*)d_out;
    int n = in_sizes[0];
    int n4 = n / 4;
    const int stride = NB_ACC * 256;
    int main4 = (n4 / stride) * stride;   // exactly covered by k_accum
    int lo = main4 * 4;

    if (main4 > 0)
        k_accum<<<NB_ACC, 256>>>((const float4*)lh, (const int4*)tt,
                                 (const int4*)ev, main4);
    if (lo < n)
        k_accum_tail<<<128, 256>>>(lh, tt, ev, lo, n);

    k_part<<<NT, TILE>>>();
    k_fused<<<NT, TILE>>>(out);
}